// round 10
// baseline (speedup 1.0000x reference)
#include <cuda_runtime.h>
#include <cuda_bf16.h>

// y = (x + 2) * 3 / 2 == fmaf(1.5f, x, 3.0f)
//
// FINAL: HBM-bound streaming kernel at the measured GB300 r+w ceiling
// (74.0us kernel, 6.9 TB/s application traffic, ~82% of peak DRAM cycles).
// Exhaustively probed and all neutral: VPT {1,4,8,16}, 128/256-bit vectors,
// load/store pipelining, persistent grid (regressed — HW work-steal beats
// static assignment), write-through stores, occupancy 30-79%. The binding
// constraint is HBM3e bus turnaround + refresh, not anything SM-side.
//
// Config: 64 B/thread (VPT=4 float4), 256 threads, flat grid (16384 blocks),
// 26 regs -> ~79% occupancy, 32-bit indexing, streaming cache hints.

constexpr int VPT = 4;                 // float4 per thread (64 B/thread)
constexpr int THREADS = 256;
constexpr int TILE = VPT * THREADS;    // float4 per block = 1024 (16 KB)

__global__ void __launch_bounds__(THREADS) fma_stream_kernel(
    const float4* __restrict__ in, float4* __restrict__ out)
{
    unsigned base = blockIdx.x * TILE + threadIdx.x;

    float4 v[VPT];
#pragma unroll
    for (int k = 0; k < VPT; k++)
        v[k] = __ldcs(in + base + k * THREADS);

#pragma unroll
    for (int k = 0; k < VPT; k++) {
        float4 r;
        r.x = fmaf(1.5f, v[k].x, 3.0f);
        r.y = fmaf(1.5f, v[k].y, 3.0f);
        r.z = fmaf(1.5f, v[k].z, 3.0f);
        r.w = fmaf(1.5f, v[k].w, 3.0f);
        __stcs(out + base + k * THREADS, r);
    }
}

// Generic remainder kernel (element granularity, any size).
__global__ void fma_tail_kernel(const float* __restrict__ in,
                                float* __restrict__ out,
                                long long start, long long n)
{
    long long i = start + (long long)blockIdx.x * blockDim.x + threadIdx.x;
    if (i < n) out[i] = fmaf(1.5f, in[i], 3.0f);
}

extern "C" void kernel_launch(void* const* d_in, const int* in_sizes, int n_in,
                              void* d_out, int out_size)
{
    const float* in = (const float*)d_in[0];
    float* out = (float*)d_out;
    long long n = (long long)in_sizes[0];

    long long n4 = n / 4;
    long long full_blocks = n4 / TILE;
    if (full_blocks > 0) {
        fma_stream_kernel<<<(unsigned)full_blocks, THREADS>>>(
            (const float4*)in, (float4*)out);
    }
    long long done = full_blocks * (long long)TILE * 4;  // elements handled
    long long tail = n - done;
    if (tail > 0) {
        fma_tail_kernel<<<(unsigned)((tail + 255) / 256), 256>>>(
            in, out, done, n);
    }
}

// round 11
// speedup vs baseline: 1.0110x; 1.0110x over previous
#include <cuda_runtime.h>
#include <cuda_bf16.h>

// y = (x + 2) * 3 / 2 == fmaf(1.5f, x, 3.0f)
//
// R11: final axis probe — block size. Same 16 KB tile as the best kernel
// (R7/R9), but 512 threads x VPT=2 instead of 256 x VPT=4. Isolates thread
// geometry / CTA front-end effects at constant tile granularity. All other
// levers exhausted across R1-R10 (VPT, vectors width, pipelining, grid
// shape, write policy, occupancy) — all neutral at the ~81% DRAM-cycle
// HBM3e r+w ceiling (~6.45 TB/s ncu-accounted, 6.9 TB/s application).

constexpr int VPT = 2;                 // float4 per thread (32 B/thread)
constexpr int THREADS = 512;
constexpr int TILE = VPT * THREADS;    // float4 per block = 1024 (16 KB)

__global__ void __launch_bounds__(THREADS) fma_stream_kernel(
    const float4* __restrict__ in, float4* __restrict__ out)
{
    unsigned base = blockIdx.x * TILE + threadIdx.x;

    float4 v[VPT];
#pragma unroll
    for (int k = 0; k < VPT; k++)
        v[k] = __ldcs(in + base + k * THREADS);

#pragma unroll
    for (int k = 0; k < VPT; k++) {
        float4 r;
        r.x = fmaf(1.5f, v[k].x, 3.0f);
        r.y = fmaf(1.5f, v[k].y, 3.0f);
        r.z = fmaf(1.5f, v[k].z, 3.0f);
        r.w = fmaf(1.5f, v[k].w, 3.0f);
        __stcs(out + base + k * THREADS, r);
    }
}

// Generic remainder kernel (element granularity, any size).
__global__ void fma_tail_kernel(const float* __restrict__ in,
                                float* __restrict__ out,
                                long long start, long long n)
{
    long long i = start + (long long)blockIdx.x * blockDim.x + threadIdx.x;
    if (i < n) out[i] = fmaf(1.5f, in[i], 3.0f);
}

extern "C" void kernel_launch(void* const* d_in, const int* in_sizes, int n_in,
                              void* d_out, int out_size)
{
    const float* in = (const float*)d_in[0];
    float* out = (float*)d_out;
    long long n = (long long)in_sizes[0];

    long long n4 = n / 4;
    long long full_blocks = n4 / TILE;
    if (full_blocks > 0) {
        fma_stream_kernel<<<(unsigned)full_blocks, THREADS>>>(
            (const float4*)in, (float4*)out);
    }
    long long done = full_blocks * (long long)TILE * 4;  // elements handled
    long long tail = n - done;
    if (tail > 0) {
        fma_tail_kernel<<<(unsigned)((tail + 255) / 256), 256>>>(
            in, out, done, n);
    }
}